// round 14
// baseline (speedup 1.0000x reference)
#include <cuda_runtime.h>
#include <cuda_bf16.h>
#include <mma.h>
#include <math.h>
#include <stdint.h>

using namespace nvcuda;

#define E_     8
#define B_     4096
#define D_IN_  1024
#define D_HID_ 2048
#define D_OUT_ 1024
#define G_HID_ 128
#define K_     2
#define PAIR_CAP 9216

// ==================== f32x2 helpers (repair path) ====================
__device__ __forceinline__ unsigned long long packf2(float lo, float hi) {
    unsigned long long r;
    asm("mov.b64 %0, {%1, %2};" : "=l"(r) : "f"(lo), "f"(hi));
    return r;
}
__device__ __forceinline__ void unpackf2(unsigned long long v, float& lo, float& hi) {
    asm("mov.b64 {%0, %1}, %2;" : "=f"(lo), "=f"(hi) : "l"(v));
}
#define FMA2(acc, a, b) \
    asm("fma.rn.f32x2 %0, %1, %2, %0;" : "+l"(acc) : "l"(a), "l"(b))

__device__ __forceinline__ void split2(float a, float b, uint32_t& hi, uint32_t& lo) {
    __nv_bfloat16 ha = __float2bfloat16_rn(a), hb = __float2bfloat16_rn(b);
    float ra = a - __bfloat162float(ha);
    float rb = b - __bfloat162float(hb);
    __nv_bfloat16 la = __float2bfloat16_rn(ra), lb = __float2bfloat16_rn(rb);
    hi = (uint32_t)__bfloat16_as_ushort(ha) | ((uint32_t)__bfloat16_as_ushort(hb) << 16);
    lo = (uint32_t)__bfloat16_as_ushort(la) | ((uint32_t)__bfloat16_as_ushort(lb) << 16);
}

// ==================== device scratch ====================
__device__ int   g_counts[E_];
__device__ int   g_offsets[E_];      // padded to 128
__device__ int   g_cursor[E_];
__device__ int   g_tok_e[B_ * K_];
__device__ float g_tok_s[B_ * K_];
__device__ int   g_tok_pos[B_ * K_];
__device__ int   g_pair_token[PAIR_CAP];
__device__ float g_entropy[B_];
__device__ int   g_badL[3];

__device__ __align__(16) __nv_bfloat16 g_x_hi[(size_t)B_ * D_IN_];
__device__ __align__(16) __nv_bfloat16 g_x_lo[(size_t)B_ * D_IN_];
__device__ __align__(16) __nv_bfloat16 g_w1t_hi[(size_t)E_ * D_HID_ * D_IN_];
__device__ __align__(16) __nv_bfloat16 g_w1t_lo[(size_t)E_ * D_HID_ * D_IN_];
__device__ __align__(16) __nv_bfloat16 g_w2t_hi[(size_t)E_ * D_HID_ * D_HID_];
__device__ __align__(16) __nv_bfloat16 g_w2t_lo[(size_t)E_ * D_HID_ * D_HID_];
__device__ __align__(16) __nv_bfloat16 g_w3t_hi[(size_t)E_ * D_OUT_ * D_HID_];
__device__ __align__(16) __nv_bfloat16 g_w3t_lo[(size_t)E_ * D_OUT_ * D_HID_];
__device__ __align__(16) __nv_bfloat16 g_h1_hi[(size_t)PAIR_CAP * D_HID_];
__device__ __align__(16) __nv_bfloat16 g_h1_lo[(size_t)PAIR_CAP * D_HID_];
__device__ __align__(16) __nv_bfloat16 g_h2_hi[(size_t)PAIR_CAP * D_HID_];
__device__ __align__(16) __nv_bfloat16 g_h2_lo[(size_t)PAIR_CAP * D_HID_];
__device__ __align__(16) float g_h1f[(size_t)PAIR_CAP * D_HID_];
__device__ __align__(16) float g_h2f[(size_t)PAIR_CAP * D_HID_];
__device__ __align__(16) float g_raw[(size_t)PAIR_CAP * D_HID_];
__device__ __align__(16) float g_opair[(size_t)PAIR_CAP * D_OUT_];

__device__ __forceinline__ int expert_of(int row) {
    int e = 0;
    #pragma unroll
    for (int i = 1; i < E_; i++) if (row >= g_offsets[i]) e = i;
    return e;
}

// ==================== small kernels ====================
__global__ void init_kernel() {
    int i = blockIdx.x * 256 + threadIdx.x;
    if (i < PAIR_CAP) g_pair_token[i] = 0;
    if (i < E_) { g_counts[i] = 0; g_cursor[i] = 0; }
    if (i < 3) g_badL[i] = 0;
}

__global__ __launch_bounds__(256)
void prep_x(const float* __restrict__ x) {
    int i = blockIdx.x * 256 + threadIdx.x;
    float v = x[i];
    __nv_bfloat16 h = __float2bfloat16_rn(v);
    g_x_hi[i] = h;
    g_x_lo[i] = __float2bfloat16_rn(v - __bfloat162float(h));
}

// W[e][KD][ND] -> Wt[e][ND][KD] hi/lo (verified by round-8 probe)
__global__ __launch_bounds__(256)
void prep_w(const float* __restrict__ W, __nv_bfloat16* __restrict__ Whi,
            __nv_bfloat16* __restrict__ Wlo, int KD, int ND)
{
    __shared__ float t[32][33];
    const int e = blockIdx.z;
    const float* Wb = W + (size_t)e * KD * ND;
    __nv_bfloat16* Hh = Whi + (size_t)e * KD * ND;
    __nv_bfloat16* Hl = Wlo + (size_t)e * KD * ND;
    const int n0 = blockIdx.x * 32, k0 = blockIdx.y * 32;
    const int tx = threadIdx.x, ty = threadIdx.y;
    #pragma unroll
    for (int i = 0; i < 4; i++) {
        int kl = ty + i * 8;
        t[kl][tx] = Wb[(size_t)(k0 + kl) * ND + n0 + tx];
    }
    __syncthreads();
    #pragma unroll
    for (int i = 0; i < 4; i++) {
        int nl = ty + i * 8;
        float v = t[tx][nl];
        __nv_bfloat16 h = __float2bfloat16_rn(v);
        __nv_bfloat16 l = __float2bfloat16_rn(v - __bfloat162float(h));
        size_t o = (size_t)(n0 + nl) * KD + k0 + tx;
        Hh[o] = h; Hl[o] = l;
    }
}

__global__ __launch_bounds__(128)
void gate_kernel(const float* __restrict__ x,
                 const float* __restrict__ Wg1, const float* __restrict__ bg1,
                 const float* __restrict__ Wg2, const float* __restrict__ bg2,
                 const float* __restrict__ Wg3, const float* __restrict__ bg3,
                 float* __restrict__ out, long long out_sz)
{
    __shared__ __align__(16) float xs[8][D_IN_];
    __shared__ float s_g1[8][G_HID_];
    __shared__ float s_g2[8][G_HID_];
    __shared__ float s_lg[8][E_];

    const int tid = threadIdx.x;
    const int t0  = blockIdx.x * 8;

    const float4* xg  = reinterpret_cast<const float4*>(x + (size_t)t0 * D_IN_);
    float4*       xsv = reinterpret_cast<float4*>(&xs[0][0]);
    #pragma unroll
    for (int i = 0; i < (8 * D_IN_ / 4) / 128; i++)
        xsv[tid + i * 128] = xg[tid + i * 128];
    __syncthreads();

    float acc[8];
    #pragma unroll
    for (int t = 0; t < 8; t++) acc[t] = 0.f;
    for (int i = 0; i < D_IN_; i++) {
        float w = Wg1[i * G_HID_ + tid];
        #pragma unroll
        for (int t = 0; t < 8; t++) acc[t] = fmaf(xs[t][i], w, acc[t]);
    }
    {
        float b = bg1[tid];
        #pragma unroll
        for (int t = 0; t < 8; t++) s_g1[t][tid] = fmaxf(acc[t] + b, 0.f);
    }
    __syncthreads();

    #pragma unroll
    for (int t = 0; t < 8; t++) acc[t] = 0.f;
    for (int i = 0; i < G_HID_; i++) {
        float w = Wg2[i * G_HID_ + tid];
        #pragma unroll
        for (int t = 0; t < 8; t++) acc[t] = fmaf(s_g1[t][i], w, acc[t]);
    }
    {
        float b = bg2[tid];
        #pragma unroll
        for (int t = 0; t < 8; t++) s_g2[t][tid] = fmaxf(acc[t] + b, 0.f);
    }
    __syncthreads();

    if (tid < 64) {
        int t = tid >> 3, e = tid & 7;
        float a = bg3[e];
        for (int i = 0; i < G_HID_; i++)
            a = fmaf(s_g2[t][i], Wg3[i * E_ + e], a);
        s_lg[t][e] = a;
    }
    __syncthreads();

    if (tid < 8) {
        const int t   = tid;
        const int tok = t0 + t;
        float p[E_];
        float mx = s_lg[t][0];
        #pragma unroll
        for (int e = 1; e < E_; e++) mx = fmaxf(mx, s_lg[t][e]);
        float s = 0.f;
        #pragma unroll
        for (int e = 0; e < E_; e++) { p[e] = expf(s_lg[t][e] - mx); s += p[e]; }
        float inv = 1.f / s;
        float ent = 0.f;
        #pragma unroll
        for (int e = 0; e < E_; e++) { p[e] *= inv; ent -= p[e] * logf(p[e] + 1e-9f); }
        g_entropy[tok] = ent;

        int i1 = 0;
        #pragma unroll
        for (int e = 1; e < E_; e++) if (p[e] > p[i1]) i1 = e;
        int i2 = (i1 == 0) ? 1 : 0;
        #pragma unroll
        for (int e = 0; e < E_; e++) if (e != i1 && p[e] > p[i2]) i2 = e;

        float s1 = p[i1], s2 = p[i2];
        atomicAdd(&g_counts[i1], 1);
        atomicAdd(&g_counts[i2], 1);
        float denom = s1 + s2 + 1e-9f;
        g_tok_e[tok * 2 + 0] = i1;
        g_tok_e[tok * 2 + 1] = i2;
        g_tok_s[tok * 2 + 0] = s1 / denom;
        g_tok_s[tok * 2 + 1] = s2 / denom;

        long long idx_off = (long long)B_ * D_OUT_ + 1;
        long long sc_off  = idx_off + (long long)B_ * K_;
        if (out_sz >= sc_off + (long long)B_ * K_) {
            out[idx_off + tok * 2 + 0] = (float)i1;
            out[idx_off + tok * 2 + 1] = (float)i2;
            out[sc_off  + tok * 2 + 0] = s1;
            out[sc_off  + tok * 2 + 1] = s2;
        }
    }
}

__global__ void offsets_kernel() {
    if (threadIdx.x == 0 && blockIdx.x == 0) {
        int off = 0;
        for (int e = 0; e < E_; e++) {
            g_offsets[e] = off;
            g_cursor[e]  = off;
            off += (g_counts[e] + 127) & ~127;
        }
    }
}

__global__ void scatter_kernel() {
    int tok = blockIdx.x * blockDim.x + threadIdx.x;
    if (tok >= B_) return;
    #pragma unroll
    for (int k = 0; k < K_; k++) {
        int e = g_tok_e[tok * 2 + k];
        int pos = atomicAdd(&g_cursor[e], 1);
        g_pair_token[pos] = tok;
        g_tok_pos[tok * 2 + k] = pos;
    }
}

// ==================== wmma engine ====================
// CTA 128x128, 512 threads (16 warps, 4x4), warp tile 32x32. BK=32, single-buffer staging.
template<int KDIM, int NDIM, int LAYER>
__global__ __launch_bounds__(512)
void wmma_gemm()
{
    const int e   = blockIdx.z;
    const int cnt = g_counts[e];
    const int m0  = blockIdx.y * 128;
    if (m0 >= cnt) return;
    const int off = g_offsets[e];
    const int n0  = blockIdx.x * 128;

    __shared__ __align__(16) __nv_bfloat16 sAh[128 * 32];
    __shared__ __align__(16) __nv_bfloat16 sAl[128 * 32];
    __shared__ __align__(16) __nv_bfloat16 sBh[128 * 32];
    __shared__ __align__(16) __nv_bfloat16 sBl[128 * 32];

    const __nv_bfloat16* Ah = (LAYER == 1) ? g_x_hi : (LAYER == 2 ? g_h1_hi : g_h2_hi);
    const __nv_bfloat16* Al = (LAYER == 1) ? g_x_lo : (LAYER == 2 ? g_h1_lo : g_h2_lo);
    const __nv_bfloat16* Wh = (LAYER == 1) ? g_w1t_hi : (LAYER == 2 ? g_w2t_hi : g_w3t_hi);
    const __nv_bfloat16* Wl = (LAYER == 1) ? g_w1t_lo : (LAYER == 2 ? g_w2t_lo : g_w3t_lo);
    float* __restrict__ raw = (LAYER == 3) ? g_opair : g_raw;   // raw acc (bias/relu later)

    const int u    = threadIdx.x;      // 0..511
    const int srow = u >> 2;           // 0..127
    const int sch  = u & 3;            // chunk of 8 bf16

    int ar = m0 + srow; if (ar >= cnt) ar = cnt - 1;
    const size_t abase = (LAYER == 1) ? (size_t)g_pair_token[off + ar] * KDIM
                                      : (size_t)(off + ar) * KDIM;
    const uint4* gAh = reinterpret_cast<const uint4*>(Ah + abase + sch * 8);
    const uint4* gAl = reinterpret_cast<const uint4*>(Al + abase + sch * 8);
    const size_t bbase = ((size_t)e * NDIM + n0 + srow) * KDIM + sch * 8;
    const uint4* gBh = reinterpret_cast<const uint4*>(Wh + bbase);
    const uint4* gBl = reinterpret_cast<const uint4*>(Wl + bbase);

    const int wid = u >> 5;
    const int wr  = wid & 3;           // row slab (32 rows)
    const int wc  = wid >> 2;          // col slab (32 cols)

    wmma::fragment<wmma::accumulator, 16, 16, 16, float> acc[2][2];
    #pragma unroll
    for (int i = 0; i < 2; i++)
        #pragma unroll
        for (int j = 0; j < 2; j++)
            wmma::fill_fragment(acc[i][j], 0.f);

    uint4 vah = gAh[0], val = gAl[0], vbh = gBh[0], vbl = gBl[0];

    const int NT = KDIM / 32;
    for (int t = 0; t < NT; t++) {
        __syncthreads();
        reinterpret_cast<uint4*>(sAh)[u] = vah;
        reinterpret_cast<uint4*>(sAl)[u] = val;
        reinterpret_cast<uint4*>(sBh)[u] = vbh;
        reinterpret_cast<uint4*>(sBl)[u] = vbl;
        __syncthreads();
        if (t + 1 < NT) {
            vah = gAh[(t + 1) * 4];
            val = gAl[(t + 1) * 4];
            vbh = gBh[(t + 1) * 4];
            vbl = gBl[(t + 1) * 4];
        }
        #pragma unroll
        for (int ks = 0; ks < 2; ks++) {
            wmma::fragment<wmma::matrix_a, 16, 16, 16, __nv_bfloat16, wmma::row_major> ah[2], al[2];
            wmma::fragment<wmma::matrix_b, 16, 16, 16, __nv_bfloat16, wmma::col_major> bh[2], bl[2];
            #pragma unroll
            for (int i = 0; i < 2; i++) {
                const __nv_bfloat16* pa = sAh + (wr * 32 + i * 16) * 32 + ks * 16;
                const __nv_bfloat16* pl = sAl + (wr * 32 + i * 16) * 32 + ks * 16;
                wmma::load_matrix_sync(ah[i], pa, 32);
                wmma::load_matrix_sync(al[i], pl, 32);
            }
            #pragma unroll
            for (int j = 0; j < 2; j++) {
                const __nv_bfloat16* pb = sBh + (wc * 32 + j * 16) * 32 + ks * 16;
                const __nv_bfloat16* pq = sBl + (wc * 32 + j * 16) * 32 + ks * 16;
                wmma::load_matrix_sync(bh[j], pb, 32);
                wmma::load_matrix_sync(bl[j], pq, 32);
            }
            #pragma unroll
            for (int i = 0; i < 2; i++)
                #pragma unroll
                for (int j = 0; j < 2; j++) {
                    wmma::mma_sync(acc[i][j], ah[i], bh[j], acc[i][j]);
                    wmma::mma_sync(acc[i][j], ah[i], bl[j], acc[i][j]);
                    wmma::mma_sync(acc[i][j], al[i], bh[j], acc[i][j]);
                }
        }
    }

    #pragma unroll
    for (int i = 0; i < 2; i++)
        #pragma unroll
        for (int j = 0; j < 2; j++) {
            float* dst = raw + (size_t)(off + m0 + wr * 32 + i * 16) * NDIM
                             + (n0 + wc * 32 + j * 16);
            wmma::store_matrix_sync(dst, acc[i][j], NDIM, wmma::mem_row_major);
        }
}

// ==================== epilogue kernels ====================
// layers 1/2: h = relu(raw + bias); write fp32 + hi/lo
template<int L>
__global__ __launch_bounds__(256)
void epi12(const float* __restrict__ bstack)
{
    const int ND = D_HID_;
    int idx = blockIdx.x * 256 + threadIdx.x;     // < PAIR_CAP * D_HID
    int row = idx / ND, col = idx - row * ND;
    int e = expert_of(row);
    float v = fmaxf(g_raw[idx] + bstack[(size_t)e * ND + col], 0.f);
    float* hf = (L == 1) ? g_h1f : g_h2f;
    __nv_bfloat16* hh = (L == 1) ? g_h1_hi : g_h2_hi;
    __nv_bfloat16* hl = (L == 1) ? g_h1_lo : g_h2_lo;
    hf[idx] = v;
    __nv_bfloat16 h = __float2bfloat16_rn(v);
    hh[idx] = h;
    hl[idx] = __float2bfloat16_rn(v - __bfloat162float(h));
}

// layer 3: opair = raw + bias (raw stored in g_opair already)
__global__ __launch_bounds__(256)
void epi3(const float* __restrict__ bstack)
{
    const int ND = D_OUT_;
    int idx = blockIdx.x * 256 + threadIdx.x;
    int row = idx / ND, col = idx - row * ND;
    int e = expert_of(row);
    g_opair[idx] += bstack[(size_t)e * ND + col];
}

// gated re-split after repair
template<int L>
__global__ __launch_bounds__(256)
void splitB()
{
    if (g_badL[L - 1] == 0) return;
    int idx = blockIdx.x * 256 + threadIdx.x;
    const float* hf = (L == 1) ? g_h1f : g_h2f;
    __nv_bfloat16* hh = (L == 1) ? g_h1_hi : g_h2_hi;
    __nv_bfloat16* hl = (L == 1) ? g_h1_lo : g_h2_lo;
    float v = hf[idx];
    __nv_bfloat16 h = __float2bfloat16_rn(v);
    hh[idx] = h;
    hl[idx] = __float2bfloat16_rn(v - __bfloat162float(h));
}

// ==================== per-layer verify ====================
template<int L>
__global__ __launch_bounds__(256)
void verify_layer(const float* __restrict__ x,
                  const float* __restrict__ W, const float* __restrict__ b)
{
    constexpr int KD = (L == 1) ? D_IN_ : D_HID_;
    constexpr int ND = (L == 3) ? D_OUT_ : D_HID_;
    __shared__ float red[256];
    __shared__ int s_bad;
    const int tid = threadIdx.x;
    if (tid == 0) s_bad = 0;
    __syncthreads();

    const int r  = (blockIdx.x >= 8) ? 101 : 0;
    const int cg = blockIdx.x & 7;

    int e = -1;
    for (int i = 0; i < E_; i++)
        if (g_offsets[i] <= r && r < g_offsets[i] + g_counts[i]) e = i;
    if (e < 0) { if (tid == 0) atomicOr(&g_badL[L - 1], 1); return; }

    const int col = cg * 32 + (tid & 31);
    const int seg = tid >> 5;
    const int klo = seg * (KD / 8), khi = klo + (KD / 8);

    float partial = 0.f;
    if (L == 1) {
        const int tok = g_pair_token[r];
        for (int k = klo; k < khi; k++)
            partial = fmaf(x[(size_t)tok * KD + k], W[((size_t)e * KD + k) * ND + col], partial);
    } else {
        const float* hf = (L == 2) ? g_h1f : g_h2f;
        for (int k = klo; k < khi; k++)
            partial = fmaf(hf[(size_t)r * KD + k], W[((size_t)e * KD + k) * ND + col], partial);
    }
    red[tid] = partial;
    __syncthreads();
    if (seg == 0) {
        float s = b[(size_t)e * ND + col];
        #pragma unroll
        for (int q = 0; q < 8; q++) s += red[(tid & 31) + q * 32];
        if (L < 3) s = fmaxf(s, 0.f);
        float got;
        if (L == 1)      got = g_h1f[(size_t)r * ND + col];
        else if (L == 2) got = g_h2f[(size_t)r * ND + col];
        else             got = g_opair[(size_t)r * ND + col];
        if (!(fabsf(got - s) <= 5e-3f * (fabsf(s) + 0.1f))) s_bad = 1;
    }
    __syncthreads();
    if (tid == 0 && s_bad) atomicOr(&g_badL[L - 1], 1);
}

// ==================== f32x2 repair GEMM (round-13 proven, gated) ====================
#define BM 128
#define BN 128
#define BK 8

template<int KDIM, int NDIM, int EPI, int ASRC, int LAYER>
__global__ __launch_bounds__(256)
void repair_gemm2(const float* __restrict__ xptr,
                  const float* __restrict__ Wstack,
                  const float* __restrict__ bstack)
{
    if (g_badL[LAYER - 1] == 0) return;

    const int e   = blockIdx.z;
    const int cnt = g_counts[e];
    const int m0  = blockIdx.y * BM;
    if (m0 >= cnt) return;
    const int off = g_offsets[e];
    const int n0  = blockIdx.x * BN;

    const float* __restrict__ Wb = Wstack + (size_t)e * KDIM * NDIM;
    const float* __restrict__ Abase =
        (ASRC == 0) ? xptr : (ASRC == 1 ? (const float*)g_h1f : (const float*)g_h2f);
    float* __restrict__ Obase =
        (EPI == 0) ? (ASRC == 0 ? (float*)g_h1f : (float*)g_h2f) : (float*)g_opair;

    __shared__ __align__(16) float As[2][BK][BM];
    __shared__ __align__(16) float Bs[2][BK][BN];

    const int tid   = threadIdx.x;
    const int a_row = tid >> 1;
    const int a_kq  = (tid & 1) << 2;
    const int b_k   = tid >> 5;
    const int b_n   = (tid & 31) << 2;

    int m  = m0 + a_row;
    int mm = (m < cnt) ? m : (cnt - 1);
    const float* __restrict__ Arow =
        (ASRC == 0) ? Abase + (size_t)g_pair_token[off + mm] * KDIM
                    : Abase + (size_t)(off + mm) * KDIM;

    const int tx = tid & 15;
    const int ty = tid >> 4;

    unsigned long long acc2[8][4];
    #pragma unroll
    for (int i = 0; i < 8; i++)
        #pragma unroll
        for (int p = 0; p < 4; p++) acc2[i][p] = 0ULL;

    {
        float4 av = *reinterpret_cast<const float4*>(Arow + a_kq);
        float4 bv = *reinterpret_cast<const float4*>(Wb + (size_t)b_k * NDIM + n0 + b_n);
        As[0][a_kq + 0][a_row] = av.x;
        As[0][a_kq + 1][a_row] = av.y;
        As[0][a_kq + 2][a_row] = av.z;
        As[0][a_kq + 3][a_row] = av.w;
        *reinterpret_cast<float4*>(&Bs[0][b_k][b_n]) = bv;
    }
    __syncthreads();

    const int ntiles = KDIM / BK;
    for (int t = 0; t < ntiles; ++t) {
        const int cur = t & 1;
        const int nxt = cur ^ 1;
        float4 an, bn;
        if (t + 1 < ntiles) {
            const int k0 = (t + 1) * BK;
            an = *reinterpret_cast<const float4*>(Arow + k0 + a_kq);
            bn = *reinterpret_cast<const float4*>(Wb + (size_t)(k0 + b_k) * NDIM + n0 + b_n);
        }
        #pragma unroll
        for (int kk = 0; kk < BK; kk++) {
            float ar[8];
            *reinterpret_cast<float4*>(&ar[0]) = *reinterpret_cast<const float4*>(&As[cur][kk][ty * 8]);
            *reinterpret_cast<float4*>(&ar[4]) = *reinterpret_cast<const float4*>(&As[cur][kk][ty * 8 + 4]);
            unsigned long long brp[4];
            #pragma unroll
            for (int p = 0; p < 4; p++)
                brp[p] = packf2(Bs[cur][kk][tx + 32 * p], Bs[cur][kk][tx + 32 * p + 16]);
            #pragma unroll
            for (int i = 0; i < 8; i++) {
                unsigned long long arr = packf2(ar[i], ar[i]);
                #pragma unroll
                for (int p = 0; p < 4; p++)
                    FMA2(acc2[i][p], arr, brp[p]);
            }
        }
        if (t + 1 < ntiles) {
            As[nxt][a_kq + 0][a_row] = an.x;
            As[nxt][a_kq + 1][a_row] = an.y;
            As[nxt][a_kq + 2][a_row] = an.z;
            As[nxt][a_kq + 3][a_row] = an.w;
            *reinterpret_cast<float4*>(&Bs[nxt][b_k][b_n]) = bn;
        }
        __syncthreads();
    }

    float bias0[4], bias1[4];
    #pragma unroll
    for (int p = 0; p < 4; p++) {
        bias0[p] = bstack[(size_t)e * NDIM + n0 + tx + 32 * p];
        bias1[p] = bstack[(size_t)e * NDIM + n0 + tx + 32 * p + 16];
    }
    #pragma unroll
    for (int i = 0; i < 8; i++) {
        int mr = m0 + ty * 8 + i;
        if (mr >= cnt) continue;
        float* orow = Obase + (size_t)(off + mr) * NDIM + n0 + tx;
        #pragma unroll
        for (int p = 0; p < 4; p++) {
            float lo, hi;
            unpackf2(acc2[i][p], lo, hi);
            float v0 = lo + bias0[p];
            float v1 = hi + bias1[p];
            if (EPI == 0) { v0 = fmaxf(v0, 0.f); v1 = fmaxf(v1, 0.f); }
            orow[32 * p]      = v0;
            orow[32 * p + 16] = v1;
        }
    }
}

// ==================== combine + finalize ====================
__global__ __launch_bounds__(256)
void combine_kernel(float* __restrict__ out)
{
    int i = blockIdx.x * 256 + threadIdx.x;
    int tok = i >> 10, c = i & 1023;
    float v = g_tok_s[tok * 2 + 0] * g_opair[(size_t)g_tok_pos[tok * 2 + 0] * D_OUT_ + c]
            + g_tok_s[tok * 2 + 1] * g_opair[(size_t)g_tok_pos[tok * 2 + 1] * D_OUT_ + c];
    out[i] = v;
}

__global__ __launch_bounds__(1024)
void finalize_kernel(float* __restrict__ out, long long out_sz)
{
    __shared__ float red[1024];
    const int tid = threadIdx.x;
    float s = 0.f;
    for (int i = tid; i < B_; i += 1024) s += g_entropy[i];
    red[tid] = s;
    __syncthreads();
    for (int st = 512; st > 0; st >>= 1) {
        if (tid < st) red[tid] += red[tid + st];
        __syncthreads();
    }
    if (tid == 0) {
        float ent_mean = red[0] / (float)B_;
        float load[E_];
        float mean = 0.f;
        for (int e = 0; e < E_; e++) {
            load[e] = (float)g_counts[e] / ((float)B_ + 1e-9f);
            mean += load[e];
        }
        mean /= (float)E_;
        float var = 0.f;
        for (int e = 0; e < E_; e++) {
            float d = load[e] - mean;
            var += d * d;
        }
        var /= (float)(E_ - 1);
        float aux = 5.0f * var + 0.1f * ent_mean;
        long long aux_off = (long long)B_ * D_OUT_;
        if (out_sz > aux_off) out[aux_off] = aux;
    }
}

// ==================== launch ====================
extern "C" void kernel_launch(void* const* d_in, const int* in_sizes, int n_in,
                              void* d_out, int out_size)
{
    const float* x   = (const float*)d_in[0];
    const float* We1 = (const float*)d_in[1];
    const float* be1 = (const float*)d_in[2];
    const float* We2 = (const float*)d_in[3];
    const float* be2 = (const float*)d_in[4];
    const float* We3 = (const float*)d_in[5];
    const float* be3 = (const float*)d_in[6];
    const float* Wg1 = (const float*)d_in[7];
    const float* bg1 = (const float*)d_in[8];
    const float* Wg2 = (const float*)d_in[9];
    const float* bg2 = (const float*)d_in[10];
    const float* Wg3 = (const float*)d_in[11];
    const float* bg3 = (const float*)d_in[12];
    float* out = (float*)d_out;
    long long out_sz = (long long)out_size;

    init_kernel<<<(PAIR_CAP + 255) / 256, 256>>>();
    gate_kernel<<<B_ / 8, 128>>>(x, Wg1, bg1, Wg2, bg2, Wg3, bg3, out, out_sz);
    offsets_kernel<<<1, 32>>>();
    scatter_kernel<<<(B_ + 255) / 256, 256>>>();

    prep_x<<<(B_ * D_IN_) / 256, 256>>>(x);
    prep_w<<<dim3(D_HID_ / 32, D_IN_  / 32, E_), dim3(32, 8)>>>(We1, g_w1t_hi, g_w1t_lo, D_IN_,  D_HID_);
    prep_w<<<dim3(D_HID_ / 32, D_HID_ / 32, E_), dim3(32, 8)>>>(We2, g_w2t_hi, g_w2t_lo, D_HID_, D_HID_);
    prep_w<<<dim3(D_OUT_ / 32, D_HID_ / 32, E_), dim3(32, 8)>>>(We3, g_w3t_hi, g_w3t_lo, D_HID_, D_OUT_);

    const int mt = PAIR_CAP / 128;   // 72
    const int nh = (PAIR_CAP * D_HID_) / 256;
    const int no = (PAIR_CAP * D_OUT_) / 256;

    // layer 1
    wmma_gemm<D_IN_,  D_HID_, 1><<<dim3(D_HID_ / 128, mt, E_), 512>>>();
    epi12<1><<<nh, 256>>>(be1);
    verify_layer<1><<<16, 256>>>(x, We1, be1);
    repair_gemm2<D_IN_,  D_HID_, 0, 0, 1><<<dim3(D_HID_ / BN, mt, E_), 256>>>(x, We1, be1);
    splitB<1><<<nh, 256>>>();

    // layer 2
    wmma_gemm<D_HID_, D_HID_, 2><<<dim3(D_HID_ / 128, mt, E_), 512>>>();
    epi12<2><<<nh, 256>>>(be2);
    verify_layer<2><<<16, 256>>>(x, We2, be2);
    repair_gemm2<D_HID_, D_HID_, 0, 1, 2><<<dim3(D_HID_ / BN, mt, E_), 256>>>(x, We2, be2);
    splitB<2><<<nh, 256>>>();

    // layer 3
    wmma_gemm<D_HID_, D_OUT_, 3><<<dim3(D_OUT_ / 128, mt, E_), 512>>>();
    epi3<<<no, 256>>>(be3);
    verify_layer<3><<<16, 256>>>(x, We3, be3);
    repair_gemm2<D_HID_, D_OUT_, 2, 2, 3><<<dim3(D_OUT_ / BN, mt, E_), 256>>>(x, We3, be3);

    combine_kernel<<<(B_ * D_OUT_) / 256, 256>>>(out);
    finalize_kernel<<<1, 1024>>>(out, out_sz);
}

// round 15
// speedup vs baseline: 2.4327x; 2.4327x over previous
#include <cuda_runtime.h>
#include <cuda_bf16.h>
#include <math.h>
#include <stdint.h>

#define E_     8
#define B_     4096
#define D_IN_  1024
#define D_HID_ 2048
#define D_OUT_ 1024
#define G_HID_ 128
#define K_     2

// ==================== f32x2 helpers ====================
__device__ __forceinline__ unsigned long long packf2(float lo, float hi) {
    unsigned long long r;
    asm("mov.b64 %0, {%1, %2};" : "=l"(r) : "f"(lo), "f"(hi));
    return r;
}
__device__ __forceinline__ void unpackf2(unsigned long long v, float& lo, float& hi) {
    asm("mov.b64 {%0, %1}, %2;" : "=f"(lo), "=f"(hi) : "l"(v));
}
#define FMA2(acc, a, b) \
    asm("fma.rn.f32x2 %0, %1, %2, %0;" : "+l"(acc) : "l"(a), "l"(b))

// ==================== device scratch ====================
__device__ int   g_counts[E_];
__device__ int   g_offsets[E_];
__device__ int   g_cursor[E_];
__device__ int   g_tok_e[B_ * K_];
__device__ float g_tok_s[B_ * K_];
__device__ int   g_tok_pos[B_ * K_];
__device__ int   g_pair_token[B_ * K_];
__device__ float g_entropy[B_];

__device__ __align__(16) float g_f1[(size_t)B_ * K_ * D_HID_];
__device__ __align__(16) float g_f2[(size_t)B_ * K_ * D_HID_];
__device__ __align__(16) float g_o_pair[(size_t)B_ * K_ * D_OUT_];

// ==================== small kernels ====================
__global__ void init_kernel() {
    if (threadIdx.x < E_) { g_counts[threadIdx.x] = 0; g_cursor[threadIdx.x] = 0; }
}

__global__ __launch_bounds__(128)
void gate_kernel(const float* __restrict__ x,
                 const float* __restrict__ Wg1, const float* __restrict__ bg1,
                 const float* __restrict__ Wg2, const float* __restrict__ bg2,
                 const float* __restrict__ Wg3, const float* __restrict__ bg3,
                 float* __restrict__ out, long long out_sz)
{
    __shared__ __align__(16) float xs[8][D_IN_];
    __shared__ float s_g1[8][G_HID_];
    __shared__ float s_g2[8][G_HID_];
    __shared__ float s_lg[8][E_];

    const int tid = threadIdx.x;
    const int t0  = blockIdx.x * 8;

    const float4* xg  = reinterpret_cast<const float4*>(x + (size_t)t0 * D_IN_);
    float4*       xsv = reinterpret_cast<float4*>(&xs[0][0]);
    #pragma unroll
    for (int i = 0; i < (8 * D_IN_ / 4) / 128; i++)
        xsv[tid + i * 128] = xg[tid + i * 128];
    __syncthreads();

    float acc[8];
    #pragma unroll
    for (int t = 0; t < 8; t++) acc[t] = 0.f;
    for (int i = 0; i < D_IN_; i++) {
        float w = Wg1[i * G_HID_ + tid];
        #pragma unroll
        for (int t = 0; t < 8; t++) acc[t] = fmaf(xs[t][i], w, acc[t]);
    }
    {
        float b = bg1[tid];
        #pragma unroll
        for (int t = 0; t < 8; t++) s_g1[t][tid] = fmaxf(acc[t] + b, 0.f);
    }
    __syncthreads();

    #pragma unroll
    for (int t = 0; t < 8; t++) acc[t] = 0.f;
    for (int i = 0; i < G_HID_; i++) {
        float w = Wg2[i * G_HID_ + tid];
        #pragma unroll
        for (int t = 0; t < 8; t++) acc[t] = fmaf(s_g1[t][i], w, acc[t]);
    }
    {
        float b = bg2[tid];
        #pragma unroll
        for (int t = 0; t < 8; t++) s_g2[t][tid] = fmaxf(acc[t] + b, 0.f);
    }
    __syncthreads();

    if (tid < 64) {
        int t = tid >> 3, e = tid & 7;
        float a = bg3[e];
        for (int i = 0; i < G_HID_; i++)
            a = fmaf(s_g2[t][i], Wg3[i * E_ + e], a);
        s_lg[t][e] = a;
    }
    __syncthreads();

    if (tid < 8) {
        const int t   = tid;
        const int tok = t0 + t;
        float p[E_];
        float mx = s_lg[t][0];
        #pragma unroll
        for (int e = 1; e < E_; e++) mx = fmaxf(mx, s_lg[t][e]);
        float s = 0.f;
        #pragma unroll
        for (int e = 0; e < E_; e++) { p[e] = expf(s_lg[t][e] - mx); s += p[e]; }
        float inv = 1.f / s;
        float ent = 0.f;
        #pragma unroll
        for (int e = 0; e < E_; e++) { p[e] *= inv; ent -= p[e] * logf(p[e] + 1e-9f); }
        g_entropy[tok] = ent;

        int i1 = 0;
        #pragma unroll
        for (int e = 1; e < E_; e++) if (p[e] > p[i1]) i1 = e;
        int i2 = (i1 == 0) ? 1 : 0;
        #pragma unroll
        for (int e = 0; e < E_; e++) if (e != i1 && p[e] > p[i2]) i2 = e;

        float s1 = p[i1], s2 = p[i2];
        atomicAdd(&g_counts[i1], 1);
        atomicAdd(&g_counts[i2], 1);
        float denom = s1 + s2 + 1e-9f;
        g_tok_e[tok * 2 + 0] = i1;
        g_tok_e[tok * 2 + 1] = i2;
        g_tok_s[tok * 2 + 0] = s1 / denom;
        g_tok_s[tok * 2 + 1] = s2 / denom;

        long long idx_off = (long long)B_ * D_OUT_ + 1;
        long long sc_off  = idx_off + (long long)B_ * K_;
        if (out_sz >= sc_off + (long long)B_ * K_) {
            out[idx_off + tok * 2 + 0] = (float)i1;
            out[idx_off + tok * 2 + 1] = (float)i2;
            out[sc_off  + tok * 2 + 0] = s1;
            out[sc_off  + tok * 2 + 1] = s2;
        }
    }
}

__global__ void offsets_kernel() {
    if (threadIdx.x == 0 && blockIdx.x == 0) {
        int off = 0;
        for (int e = 0; e < E_; e++) {
            g_offsets[e] = off;
            g_cursor[e]  = off;
            off += g_counts[e];
        }
    }
}

__global__ void scatter_kernel() {
    int tok = blockIdx.x * blockDim.x + threadIdx.x;
    if (tok >= B_) return;
    #pragma unroll
    for (int k = 0; k < K_; k++) {
        int e = g_tok_e[tok * 2 + k];
        int pos = atomicAdd(&g_cursor[e], 1);
        g_pair_token[pos] = tok;
        g_tok_pos[tok * 2 + k] = pos;
    }
}

// ==================== f32x2 packed GEMM (round-13 engine, BK=16) ====================
#define BM 128
#define BN 128
#define BK 16

// 256 threads; thread (tx=tid&15, ty=tid>>4): rows ty*8+[0,8), cols n0 + tx + 32p (+16), p=0..3.
template<int KDIM, int NDIM, int EPI, int ASRC>
__global__ __launch_bounds__(256)
void moe_gemm2(const float* __restrict__ xptr,
               const float* __restrict__ Wstack,
               const float* __restrict__ bstack)
{
    const int e   = blockIdx.z;
    const int cnt = g_counts[e];
    const int m0  = blockIdx.y * BM;
    if (m0 >= cnt) return;
    const int off = g_offsets[e];
    const int n0  = blockIdx.x * BN;

    const float* __restrict__ Wb = Wstack + (size_t)e * KDIM * NDIM;
    const float* __restrict__ Abase =
        (ASRC == 0) ? xptr : (ASRC == 1 ? (const float*)g_f1 : (const float*)g_f2);
    float* __restrict__ Obase =
        (EPI == 0) ? (ASRC == 0 ? (float*)g_f1 : (float*)g_f2) : (float*)g_o_pair;

    __shared__ __align__(16) float As[2][BK][BM];   // 2 x 16 x 128 x 4B = 16 KB
    __shared__ __align__(16) float Bs[2][BK][BN];   // 16 KB

    const int tid   = threadIdx.x;
    const int a_row = tid >> 1;
    const int a_kq  = (tid & 1) << 2;   // k-chunks at a_kq and a_kq+8
    const int b_k   = tid >> 5;         // k-rows b_k and b_k+8
    const int b_n   = (tid & 31) << 2;

    int m  = m0 + a_row;
    int mm = (m < cnt) ? m : (cnt - 1);
    const float* __restrict__ Arow =
        (ASRC == 0) ? Abase + (size_t)g_pair_token[off + mm] * KDIM
                    : Abase + (size_t)(off + mm) * KDIM;

    const int tx = tid & 15;
    const int ty = tid >> 4;

    unsigned long long acc2[8][4];
    #pragma unroll
    for (int i = 0; i < 8; i++)
        #pragma unroll
        for (int p = 0; p < 4; p++) acc2[i][p] = 0ULL;

    auto store_tile = [&](int buf, const float4& av0, const float4& av1,
                          const float4& bv0, const float4& bv1) {
        As[buf][a_kq + 0][a_row] = av0.x;
        As[buf][a_kq + 1][a_row] = av0.y;
        As[buf][a_kq + 2][a_row] = av0.z;
        As[buf][a_kq + 3][a_row] = av0.w;
        As[buf][a_kq + 8][a_row]  = av1.x;
        As[buf][a_kq + 9][a_row]  = av1.y;
        As[buf][a_kq + 10][a_row] = av1.z;
        As[buf][a_kq + 11][a_row] = av1.w;
        *reinterpret_cast<float4*>(&Bs[buf][b_k][b_n])     = bv0;
        *reinterpret_cast<float4*>(&Bs[buf][b_k + 8][b_n]) = bv1;
    };

    // prologue: tile 0
    {
        float4 av0 = *reinterpret_cast<const float4*>(Arow + a_kq);
        float4 av1 = *reinterpret_cast<const float4*>(Arow + a_kq + 8);
        float4 bv0 = *reinterpret_cast<const float4*>(Wb + (size_t)b_k * NDIM + n0 + b_n);
        float4 bv1 = *reinterpret_cast<const float4*>(Wb + (size_t)(b_k + 8) * NDIM + n0 + b_n);
        store_tile(0, av0, av1, bv0, bv1);
    }
    __syncthreads();

    const int ntiles = KDIM / BK;
    for (int t = 0; t < ntiles; ++t) {
        const int cur = t & 1;
        const int nxt = cur ^ 1;
        float4 an0, an1, bn0, bn1;
        if (t + 1 < ntiles) {
            const int k0 = (t + 1) * BK;
            an0 = *reinterpret_cast<const float4*>(Arow + k0 + a_kq);
            an1 = *reinterpret_cast<const float4*>(Arow + k0 + a_kq + 8);
            bn0 = *reinterpret_cast<const float4*>(Wb + (size_t)(k0 + b_k) * NDIM + n0 + b_n);
            bn1 = *reinterpret_cast<const float4*>(Wb + (size_t)(k0 + b_k + 8) * NDIM + n0 + b_n);
        }
        #pragma unroll
        for (int kk = 0; kk < BK; kk++) {
            float ar[8];
            *reinterpret_cast<float4*>(&ar[0]) = *reinterpret_cast<const float4*>(&As[cur][kk][ty * 8]);
            *reinterpret_cast<float4*>(&ar[4]) = *reinterpret_cast<const float4*>(&As[cur][kk][ty * 8 + 4]);
            unsigned long long brp[4];
            #pragma unroll
            for (int p = 0; p < 4; p++)
                brp[p] = packf2(Bs[cur][kk][tx + 32 * p], Bs[cur][kk][tx + 32 * p + 16]);
            #pragma unroll
            for (int i = 0; i < 8; i++) {
                unsigned long long arr = packf2(ar[i], ar[i]);
                #pragma unroll
                for (int p = 0; p < 4; p++)
                    FMA2(acc2[i][p], arr, brp[p]);
            }
        }
        if (t + 1 < ntiles) store_tile(nxt, an0, an1, bn0, bn1);
        __syncthreads();
    }

    // epilogue: cols n0 + tx + 32p (+16)
    float bias0[4], bias1[4];
    #pragma unroll
    for (int p = 0; p < 4; p++) {
        bias0[p] = bstack[(size_t)e * NDIM + n0 + tx + 32 * p];
        bias1[p] = bstack[(size_t)e * NDIM + n0 + tx + 32 * p + 16];
    }
    #pragma unroll
    for (int i = 0; i < 8; i++) {
        int mr = m0 + ty * 8 + i;
        if (mr >= cnt) continue;
        float* orow = Obase + (size_t)(off + mr) * NDIM + n0 + tx;
        #pragma unroll
        for (int p = 0; p < 4; p++) {
            float lo, hi;
            unpackf2(acc2[i][p], lo, hi);
            float v0 = lo + bias0[p];
            float v1 = hi + bias1[p];
            if (EPI == 0) { v0 = fmaxf(v0, 0.f); v1 = fmaxf(v1, 0.f); }
            orow[32 * p]      = v0;
            orow[32 * p + 16] = v1;
        }
    }
}

// ==================== combine + finalize ====================
__global__ __launch_bounds__(256)
void combine_kernel(float* __restrict__ out)
{
    int i = blockIdx.x * 256 + threadIdx.x;
    int tok = i >> 10, c = i & 1023;
    float v = g_tok_s[tok * 2 + 0] * g_o_pair[(size_t)g_tok_pos[tok * 2 + 0] * D_OUT_ + c]
            + g_tok_s[tok * 2 + 1] * g_o_pair[(size_t)g_tok_pos[tok * 2 + 1] * D_OUT_ + c];
    out[i] = v;
}

__global__ __launch_bounds__(1024)
void finalize_kernel(float* __restrict__ out, long long out_sz)
{
    __shared__ float red[1024];
    const int tid = threadIdx.x;
    float s = 0.f;
    for (int i = tid; i < B_; i += 1024) s += g_entropy[i];
    red[tid] = s;
    __syncthreads();
    for (int st = 512; st > 0; st >>= 1) {
        if (tid < st) red[tid] += red[tid + st];
        __syncthreads();
    }
    if (tid == 0) {
        float ent_mean = red[0] / (float)B_;
        float load[E_];
        float mean = 0.f;
        for (int e = 0; e < E_; e++) {
            load[e] = (float)g_counts[e] / ((float)B_ + 1e-9f);
            mean += load[e];
        }
        mean /= (float)E_;
        float var = 0.f;
        for (int e = 0; e < E_; e++) {
            float d = load[e] - mean;
            var += d * d;
        }
        var /= (float)(E_ - 1);
        float aux = 5.0f * var + 0.1f * ent_mean;
        long long aux_off = (long long)B_ * D_OUT_;
        if (out_sz > aux_off) out[aux_off] = aux;
    }
}

// ==================== launch ====================
extern "C" void kernel_launch(void* const* d_in, const int* in_sizes, int n_in,
                              void* d_out, int out_size)
{
    const float* x   = (const float*)d_in[0];
    const float* We1 = (const float*)d_in[1];
    const float* be1 = (const float*)d_in[2];
    const float* We2 = (const float*)d_in[3];
    const float* be2 = (const float*)d_in[4];
    const float* We3 = (const float*)d_in[5];
    const float* be3 = (const float*)d_in[6];
    const float* Wg1 = (const float*)d_in[7];
    const float* bg1 = (const float*)d_in[8];
    const float* Wg2 = (const float*)d_in[9];
    const float* bg2 = (const float*)d_in[10];
    const float* Wg3 = (const float*)d_in[11];
    const float* bg3 = (const float*)d_in[12];
    float* out = (float*)d_out;
    long long out_sz = (long long)out_size;

    init_kernel<<<1, 32>>>();
    gate_kernel<<<B_ / 8, 128>>>(x, Wg1, bg1, Wg2, bg2, Wg3, bg3, out, out_sz);
    offsets_kernel<<<1, 32>>>();
    scatter_kernel<<<(B_ + 255) / 256, 256>>>();

    const int max_mt = B_ / 128;   // per-expert cnt <= B
    dim3 g1(D_HID_ / BN, max_mt, E_);
    dim3 g3(D_OUT_ / BN, max_mt, E_);

    moe_gemm2<D_IN_,  D_HID_, 0, 0><<<g1, 256>>>(x, We1, be1);
    moe_gemm2<D_HID_, D_HID_, 0, 1><<<g1, 256>>>(x, We2, be2);
    moe_gemm2<D_HID_, D_OUT_, 2, 2><<<g3, 256>>>(x, We3, be3);

    combine_kernel<<<(B_ * D_OUT_) / 256, 256>>>(out);
    finalize_kernel<<<1, 1024>>>(out, out_sz);
}

// round 16
// speedup vs baseline: 2.6672x; 1.0964x over previous
#include <cuda_runtime.h>
#include <cuda_bf16.h>
#include <math.h>
#include <stdint.h>

#define E_     8
#define B_     4096
#define D_IN_  1024
#define D_HID_ 2048
#define D_OUT_ 1024
#define G_HID_ 128
#define K_     2

// ==================== f32x2 helpers ====================
__device__ __forceinline__ unsigned long long packf2(float lo, float hi) {
    unsigned long long r;
    asm("mov.b64 %0, {%1, %2};" : "=l"(r) : "f"(lo), "f"(hi));
    return r;
}
__device__ __forceinline__ void unpackf2(unsigned long long v, float& lo, float& hi) {
    asm("mov.b64 {%0, %1}, %2;" : "=f"(lo), "=f"(hi) : "l"(v));
}
#define FMA2(acc, a, b) \
    asm("fma.rn.f32x2 %0, %1, %2, %0;" : "+l"(acc) : "l"(a), "l"(b))

// ==================== device scratch ====================
__device__ int   g_counts[E_];
__device__ int   g_offsets[E_];
__device__ int   g_cursor[E_];
__device__ int   g_tok_e[B_ * K_];
__device__ float g_tok_s[B_ * K_];
__device__ int   g_tok_pos[B_ * K_];
__device__ int   g_pair_token[B_ * K_];
__device__ float g_entropy[B_];

__device__ __align__(16) float g_f1[(size_t)B_ * K_ * D_HID_];
__device__ __align__(16) float g_f2[(size_t)B_ * K_ * D_HID_];
__device__ __align__(16) float g_o_pair[(size_t)B_ * K_ * D_OUT_];

// ==================== small kernels ====================
__global__ void init_kernel() {
    if (threadIdx.x < E_) { g_counts[threadIdx.x] = 0; g_cursor[threadIdx.x] = 0; }
}

__global__ __launch_bounds__(128)
void gate_kernel(const float* __restrict__ x,
                 const float* __restrict__ Wg1, const float* __restrict__ bg1,
                 const float* __restrict__ Wg2, const float* __restrict__ bg2,
                 const float* __restrict__ Wg3, const float* __restrict__ bg3,
                 float* __restrict__ out, long long out_sz)
{
    __shared__ __align__(16) float xs[8][D_IN_];
    __shared__ float s_g1[8][G_HID_];
    __shared__ float s_g2[8][G_HID_];
    __shared__ float s_lg[8][E_];

    const int tid = threadIdx.x;
    const int t0  = blockIdx.x * 8;

    const float4* xg  = reinterpret_cast<const float4*>(x + (size_t)t0 * D_IN_);
    float4*       xsv = reinterpret_cast<float4*>(&xs[0][0]);
    #pragma unroll
    for (int i = 0; i < (8 * D_IN_ / 4) / 128; i++)
        xsv[tid + i * 128] = xg[tid + i * 128];
    __syncthreads();

    float acc[8];
    #pragma unroll
    for (int t = 0; t < 8; t++) acc[t] = 0.f;
    for (int i = 0; i < D_IN_; i++) {
        float w = Wg1[i * G_HID_ + tid];
        #pragma unroll
        for (int t = 0; t < 8; t++) acc[t] = fmaf(xs[t][i], w, acc[t]);
    }
    {
        float b = bg1[tid];
        #pragma unroll
        for (int t = 0; t < 8; t++) s_g1[t][tid] = fmaxf(acc[t] + b, 0.f);
    }
    __syncthreads();

    #pragma unroll
    for (int t = 0; t < 8; t++) acc[t] = 0.f;
    for (int i = 0; i < G_HID_; i++) {
        float w = Wg2[i * G_HID_ + tid];
        #pragma unroll
        for (int t = 0; t < 8; t++) acc[t] = fmaf(s_g1[t][i], w, acc[t]);
    }
    {
        float b = bg2[tid];
        #pragma unroll
        for (int t = 0; t < 8; t++) s_g2[t][tid] = fmaxf(acc[t] + b, 0.f);
    }
    __syncthreads();

    if (tid < 64) {
        int t = tid >> 3, e = tid & 7;
        float a = bg3[e];
        for (int i = 0; i < G_HID_; i++)
            a = fmaf(s_g2[t][i], Wg3[i * E_ + e], a);
        s_lg[t][e] = a;
    }
    __syncthreads();

    if (tid < 8) {
        const int t   = tid;
        const int tok = t0 + t;
        float p[E_];
        float mx = s_lg[t][0];
        #pragma unroll
        for (int e = 1; e < E_; e++) mx = fmaxf(mx, s_lg[t][e]);
        float s = 0.f;
        #pragma unroll
        for (int e = 0; e < E_; e++) { p[e] = expf(s_lg[t][e] - mx); s += p[e]; }
        float inv = 1.f / s;
        float ent = 0.f;
        #pragma unroll
        for (int e = 0; e < E_; e++) { p[e] *= inv; ent -= p[e] * logf(p[e] + 1e-9f); }
        g_entropy[tok] = ent;

        int i1 = 0;
        #pragma unroll
        for (int e = 1; e < E_; e++) if (p[e] > p[i1]) i1 = e;
        int i2 = (i1 == 0) ? 1 : 0;
        #pragma unroll
        for (int e = 0; e < E_; e++) if (e != i1 && p[e] > p[i2]) i2 = e;

        float s1 = p[i1], s2 = p[i2];
        atomicAdd(&g_counts[i1], 1);
        atomicAdd(&g_counts[i2], 1);
        float denom = s1 + s2 + 1e-9f;
        g_tok_e[tok * 2 + 0] = i1;
        g_tok_e[tok * 2 + 1] = i2;
        g_tok_s[tok * 2 + 0] = s1 / denom;
        g_tok_s[tok * 2 + 1] = s2 / denom;

        long long idx_off = (long long)B_ * D_OUT_ + 1;
        long long sc_off  = idx_off + (long long)B_ * K_;
        if (out_sz >= sc_off + (long long)B_ * K_) {
            out[idx_off + tok * 2 + 0] = (float)i1;
            out[idx_off + tok * 2 + 1] = (float)i2;
            out[sc_off  + tok * 2 + 0] = s1;
            out[sc_off  + tok * 2 + 1] = s2;
        }
    }
}

__global__ void offsets_kernel() {
    if (threadIdx.x == 0 && blockIdx.x == 0) {
        int off = 0;
        for (int e = 0; e < E_; e++) {
            g_offsets[e] = off;
            g_cursor[e]  = off;
            off += g_counts[e];
        }
    }
}

__global__ void scatter_kernel() {
    int tok = blockIdx.x * blockDim.x + threadIdx.x;
    if (tok >= B_) return;
    #pragma unroll
    for (int k = 0; k < K_; k++) {
        int e = g_tok_e[tok * 2 + k];
        int pos = atomicAdd(&g_cursor[e], 1);
        g_pair_token[pos] = tok;
        g_tok_pos[tok * 2 + k] = pos;
    }
}

// ==================== f32x2 packed GEMM (round-13 engine + B pre-pairing) ============
#define BM 128
#define BN 128
#define BK 8

// 256 threads; thread (tx=tid&15, ty=tid>>4): rows ty*8+[0,8), cols n0 + tx + 32p (+16).
// As[k][m] scalar (round-13 proven); Bs2[k][p*16+r] = (B[k][n0+32p+r], B[k][n0+32p+16+r]).
template<int KDIM, int NDIM, int EPI, int ASRC>
__global__ __launch_bounds__(256)
void moe_gemm2(const float* __restrict__ xptr,
               const float* __restrict__ Wstack,
               const float* __restrict__ bstack)
{
    const int e   = blockIdx.z;
    const int cnt = g_counts[e];
    const int m0  = blockIdx.y * BM;
    if (m0 >= cnt) return;
    const int off = g_offsets[e];
    const int n0  = blockIdx.x * BN;

    const float* __restrict__ Wb = Wstack + (size_t)e * KDIM * NDIM;
    const float* __restrict__ Abase =
        (ASRC == 0) ? xptr : (ASRC == 1 ? (const float*)g_f1 : (const float*)g_f2);
    float* __restrict__ Obase =
        (EPI == 0) ? (ASRC == 0 ? (float*)g_f1 : (float*)g_f2) : (float*)g_o_pair;

    __shared__ __align__(16) float  As[2][BK][BM];        // 8 KB
    __shared__ __align__(16) float2 Bs2[2][BK][BN / 2];   // 8 KB

    const int tid   = threadIdx.x;
    const int a_row = tid >> 1;
    const int a_kq  = (tid & 1) << 2;
    const int b_k   = tid >> 5;
    const int b_n   = (tid & 31) << 2;
    // B pair-slot: this thread's 4 columns share group p and half
    const int b_p    = b_n >> 5;
    const int b_r    = b_n & 31;
    const int b_half = b_r >> 4;               // 0 => lo element, 1 => hi element
    const int b_j    = b_p * 16 + (b_r & 15);  // pair index of first column

    int m  = m0 + a_row;
    int mm = (m < cnt) ? m : (cnt - 1);
    const float* __restrict__ Arow =
        (ASRC == 0) ? Abase + (size_t)g_pair_token[off + mm] * KDIM
                    : Abase + (size_t)(off + mm) * KDIM;

    const int tx = tid & 15;
    const int ty = tid >> 4;

    unsigned long long acc2[8][4];
    #pragma unroll
    for (int i = 0; i < 8; i++)
        #pragma unroll
        for (int p = 0; p < 4; p++) acc2[i][p] = 0ULL;

    auto store_tile = [&](int buf, const float4& av, const float4& bv) {
        As[buf][a_kq + 0][a_row] = av.x;
        As[buf][a_kq + 1][a_row] = av.y;
        As[buf][a_kq + 2][a_row] = av.z;
        As[buf][a_kq + 3][a_row] = av.w;
        float* c0 = reinterpret_cast<float*>(&Bs2[buf][b_k][b_j]) + b_half;
        c0[0] = bv.x;  c0[2] = bv.y;  c0[4] = bv.z;  c0[6] = bv.w;
    };

    // prologue: tile 0
    {
        float4 av = *reinterpret_cast<const float4*>(Arow + a_kq);
        float4 bv = *reinterpret_cast<const float4*>(Wb + (size_t)b_k * NDIM + n0 + b_n);
        store_tile(0, av, bv);
    }
    __syncthreads();

    const int ntiles = KDIM / BK;
    for (int t = 0; t < ntiles; ++t) {
        const int cur = t & 1;
        const int nxt = cur ^ 1;
        float4 an, bn;
        if (t + 1 < ntiles) {
            const int k0 = (t + 1) * BK;
            an = *reinterpret_cast<const float4*>(Arow + k0 + a_kq);
            bn = *reinterpret_cast<const float4*>(Wb + (size_t)(k0 + b_k) * NDIM + n0 + b_n);
        }
        #pragma unroll
        for (int kk = 0; kk < BK; kk++) {
            float ar[8];
            *reinterpret_cast<float4*>(&ar[0]) = *reinterpret_cast<const float4*>(&As[cur][kk][ty * 8]);
            *reinterpret_cast<float4*>(&ar[4]) = *reinterpret_cast<const float4*>(&As[cur][kk][ty * 8 + 4]);
            unsigned long long brp[4];
            #pragma unroll
            for (int p = 0; p < 4; p++)
                brp[p] = *reinterpret_cast<const unsigned long long*>(&Bs2[cur][kk][p * 16 + tx]);
            #pragma unroll
            for (int i = 0; i < 8; i++) {
                unsigned long long arr = packf2(ar[i], ar[i]);
                #pragma unroll
                for (int p = 0; p < 4; p++)
                    FMA2(acc2[i][p], arr, brp[p]);
            }
        }
        if (t + 1 < ntiles) store_tile(nxt, an, bn);
        __syncthreads();
    }

    // epilogue: cols n0 + tx + 32p (+16)
    float bias0[4], bias1[4];
    #pragma unroll
    for (int p = 0; p < 4; p++) {
        bias0[p] = bstack[(size_t)e * NDIM + n0 + tx + 32 * p];
        bias1[p] = bstack[(size_t)e * NDIM + n0 + tx + 32 * p + 16];
    }
    #pragma unroll
    for (int i = 0; i < 8; i++) {
        int mr = m0 + ty * 8 + i;
        if (mr >= cnt) continue;
        float* orow = Obase + (size_t)(off + mr) * NDIM + n0 + tx;
        #pragma unroll
        for (int p = 0; p < 4; p++) {
            float lo, hi;
            unpackf2(acc2[i][p], lo, hi);
            float v0 = lo + bias0[p];
            float v1 = hi + bias1[p];
            if (EPI == 0) { v0 = fmaxf(v0, 0.f); v1 = fmaxf(v1, 0.f); }
            orow[32 * p]      = v0;
            orow[32 * p + 16] = v1;
        }
    }
}

// ==================== combine + finalize ====================
__global__ __launch_bounds__(256)
void combine_kernel(float* __restrict__ out)
{
    int i = blockIdx.x * 256 + threadIdx.x;
    int tok = i >> 10, c = i & 1023;
    float v = g_tok_s[tok * 2 + 0] * g_o_pair[(size_t)g_tok_pos[tok * 2 + 0] * D_OUT_ + c]
            + g_tok_s[tok * 2 + 1] * g_o_pair[(size_t)g_tok_pos[tok * 2 + 1] * D_OUT_ + c];
    out[i] = v;
}

__global__ __launch_bounds__(1024)
void finalize_kernel(float* __restrict__ out, long long out_sz)
{
    __shared__ float red[1024];
    const int tid = threadIdx.x;
    float s = 0.f;
    for (int i = tid; i < B_; i += 1024) s += g_entropy[i];
    red[tid] = s;
    __syncthreads();
    for (int st = 512; st > 0; st >>= 1) {
        if (tid < st) red[tid] += red[tid + st];
        __syncthreads();
    }
    if (tid == 0) {
        float ent_mean = red[0] / (float)B_;
        float load[E_];
        float mean = 0.f;
        for (int e = 0; e < E_; e++) {
            load[e] = (float)g_counts[e] / ((float)B_ + 1e-9f);
            mean += load[e];
        }
        mean /= (float)E_;
        float var = 0.f;
        for (int e = 0; e < E_; e++) {
            float d = load[e] - mean;
            var += d * d;
        }
        var /= (float)(E_ - 1);
        float aux = 5.0f * var + 0.1f * ent_mean;
        long long aux_off = (long long)B_ * D_OUT_;
        if (out_sz > aux_off) out[aux_off] = aux;
    }
}

// ==================== launch ====================
extern "C" void kernel_launch(void* const* d_in, const int* in_sizes, int n_in,
                              void* d_out, int out_size)
{
    const float* x   = (const float*)d_in[0];
    const float* We1 = (const float*)d_in[1];
    const float* be1 = (const float*)d_in[2];
    const float* We2 = (const float*)d_in[3];
    const float* be2 = (const float*)d_in[4];
    const float* We3 = (const float*)d_in[5];
    const float* be3 = (const float*)d_in[6];
    const float* Wg1 = (const float*)d_in[7];
    const float* bg1 = (const float*)d_in[8];
    const float* Wg2 = (const float*)d_in[9];
    const float* bg2 = (const float*)d_in[10];
    const float* Wg3 = (const float*)d_in[11];
    const float* bg3 = (const float*)d_in[12];
    float* out = (float*)d_out;
    long long out_sz = (long long)out_size;

    init_kernel<<<1, 32>>>();
    gate_kernel<<<B_ / 8, 128>>>(x, Wg1, bg1, Wg2, bg2, Wg3, bg3, out, out_sz);
    offsets_kernel<<<1, 32>>>();
    scatter_kernel<<<(B_ + 255) / 256, 256>>>();

    const int max_mt = B_ / 128;   // per-expert cnt <= B
    dim3 g1(D_HID_ / BN, max_mt, E_);
    dim3 g3(D_OUT_ / BN, max_mt, E_);

    moe_gemm2<D_IN_,  D_HID_, 0, 0><<<g1, 256>>>(x, We1, be1);
    moe_gemm2<D_HID_, D_HID_, 0, 1><<<g1, 256>>>(x, We2, be2);
    moe_gemm2<D_HID_, D_OUT_, 2, 2><<<g3, 256>>>(x, We3, be3);

    combine_kernel<<<(B_ * D_OUT_) / 256, 256>>>(out);
    finalize_kernel<<<1, 1024>>>(out, out_sz);
}